// round 14
// baseline (speedup 1.0000x reference)
#include <cuda_runtime.h>
#include <cuda_fp16.h>
#include <math.h>
#include <stdint.h>

#define SLEN 2048
#define DM   1024
#define NHEAD 16
#define HD   64
#define BATCH 2
#define NROWS (BATCH*SLEN)   // 4096

// ---------------- scratch (device globals; no allocation allowed) ----------
__device__ __half g_xh[(size_t)NROWS*DM];          // x fp16
__device__ __half g_ah[(size_t)NROWS*DM];          // attn out fp16
__device__ __half g_wqh[(size_t)3*DM*DM];          // W_qkv^T fp16 [3072,1024]
__device__ __half g_woh[(size_t)DM*DM];            // W_out^T fp16
// q/k/v fp16, layout [B*H][S][64]
__device__ __half g_qh[(size_t)BATCH*NHEAD*SLEN*HD];
__device__ __half g_kh[(size_t)BATCH*NHEAD*SLEN*HD];
__device__ __half g_vh[(size_t)BATCH*NHEAD*SLEN*HD];

// ---------------- baseline-PTX helpers -------------------------------------
__device__ __forceinline__ uint32_t smem_u32(const void* p) {
    uint32_t a;
    asm("{ .reg .u64 t; cvta.to.shared.u64 t, %1; cvt.u32.u64 %0, t; }"
        : "=r"(a) : "l"(p));
    return a;
}
__device__ __forceinline__ void cp16(uint32_t s, const void* g) {
    asm volatile("cp.async.cg.shared.global [%0], [%1], 16;"
                 :: "r"(s), "l"(g) : "memory");
}
#define CP_COMMIT() asm volatile("cp.async.commit_group;" ::: "memory")
#define CP_WAIT2()  asm volatile("cp.async.wait_group 2;" ::: "memory")
#define CP_WAIT1()  asm volatile("cp.async.wait_group 1;" ::: "memory")
#define CP_WAIT0()  asm volatile("cp.async.wait_group 0;" ::: "memory")

__device__ __forceinline__ void ldsm4(uint32_t* r, uint32_t addr) {
    asm volatile("ldmatrix.sync.aligned.m8n8.x4.shared.b16 {%0,%1,%2,%3}, [%4];"
        : "=r"(r[0]), "=r"(r[1]), "=r"(r[2]), "=r"(r[3]) : "r"(addr));
}
__device__ __forceinline__ void ldsm4t(uint32_t* r, uint32_t addr) {
    asm volatile("ldmatrix.sync.aligned.m8n8.x4.trans.shared.b16 {%0,%1,%2,%3}, [%4];"
        : "=r"(r[0]), "=r"(r[1]), "=r"(r[2]), "=r"(r[3]) : "r"(addr));
}
// fp16 MMA, fp32 accumulate
__device__ __forceinline__ void mma_f16(float* d, const uint32_t* a,
                                        const uint32_t* b) {
    asm volatile("mma.sync.aligned.m16n8k16.row.col.f32.f16.f16.f32 "
        "{%0,%1,%2,%3}, {%4,%5,%6,%7}, {%8,%9}, {%0,%1,%2,%3};"
        : "+f"(d[0]), "+f"(d[1]), "+f"(d[2]), "+f"(d[3])
        : "r"(a[0]), "r"(a[1]), "r"(a[2]), "r"(a[3]), "r"(b[0]), "r"(b[1]));
}
// pack two fp32 -> half2 (first arg in low half)
__device__ __forceinline__ uint32_t packh(float lo, float hi) {
    __half2 h = __floats2half2_rn(lo, hi);
    return *reinterpret_cast<uint32_t*>(&h);
}

// exp2 via FFMA poly (no MUFU). z expected <= 0; clamped at -40.
__device__ __forceinline__ float fast_exp2(float z) {
    z = fmaxf(z, -40.f);
    const float km = z + 12582912.f;          // round-to-nearest int
    const int   ki = __float_as_int(km) - 0x4B400000;   // = round(z)
    const float f  = z - (km - 12582912.f);   // frac in [-0.5, 0.5]
    float p = 0.0013333558f;
    p = fmaf(p, f, 0.0096181815f);
    p = fmaf(p, f, 0.0555041087f);
    p = fmaf(p, f, 0.2402265069f);
    p = fmaf(p, f, 0.6931471806f);
    p = fmaf(p, f, 1.0f);
    return p * __int_as_float((ki + 127) << 23);
}

#define SCQ   0.18033688011112042f   // hd^-0.5 * log2(e), folded into Q

// ---------------------------------------------------------------------------
// Convert fp32 -> fp16 (activations; single precision level)
// ---------------------------------------------------------------------------
__global__ __launch_bounds__(256) void conv_x_kernel(
    const float* __restrict__ src, __half* __restrict__ dst, int n)
{
    int i = (blockIdx.x * 256 + threadIdx.x) * 4;
    if (i >= n) return;
    float4 v = *(const float4*)(src + i);
    uint2 o;
    o.x = packh(v.x, v.y);
    o.y = packh(v.z, v.w);
    *(uint2*)(dst + i) = o;
}

// ---------------------------------------------------------------------------
// Transpose: W[1024, N] fp32 -> Wt [N, 1024] fp16
// ---------------------------------------------------------------------------
__global__ __launch_bounds__(256) void conv_wt_kernel(
    const float* __restrict__ W, __half* __restrict__ hi, int N)
{
    __shared__ float t[32][33];
    const int n0 = blockIdx.x * 32, k0 = blockIdx.y * 32;
    const int tx = threadIdx.x & 31, ty = threadIdx.x >> 5;
    #pragma unroll
    for (int i = 0; i < 4; i++)
        t[ty + i * 8][tx] = W[(size_t)(k0 + ty + i * 8) * N + n0 + tx];
    __syncthreads();
    #pragma unroll
    for (int i = 0; i < 4; i++) {
        const int n = n0 + ty + i * 8;
        hi[(size_t)n * DM + k0 + tx] = __float2half_rn(t[tx][ty + i * 8]);
    }
}

// ---------------------------------------------------------------------------
// HMMA pure-fp16 GEMM: D = A * B^T, 128x128 CTA tile, 8 warps (4m x 2n),
// m16n8k16, K-chunk 32, 4-stage single-sync cp.async pipeline.
// Stage = 2 arrays x 128 rows x 80B = 20480B; 4 stages = 80KB -> 2 CTAs/SM.
// DO_QKV: fused RoPE + fp16 scatter to g_q/k/v.
// ---------------------------------------------------------------------------
#define GST   20480
#define GARR  10240
template<int DO_QKV>
__global__ __launch_bounds__(256, 2) void hmma_gemm_kernel(
    const __half* __restrict__ A, const __half* __restrict__ B,
    const float* __restrict__ rc, const float* __restrict__ rs,
    float* __restrict__ outp)
{
    extern __shared__ char smem[];
    const uint32_t sb = smem_u32(smem);
    const int tid = threadIdx.x, lane = tid & 31, wid = tid >> 5;
    const int wm = wid >> 1, wn = wid & 1;
    const int row0 = blockIdx.y * 128, col0 = blockIdx.x * 128;

    float acc[2][8][4];
    #pragma unroll
    for (int m = 0; m < 2; m++)
        #pragma unroll
        for (int n = 0; n < 8; n++)
            #pragma unroll
            for (int q = 0; q < 4; q++) acc[m][n][q] = 0.f;

    const int lrow = tid >> 1, kh = tid & 1;
    const __half* ga0 = A + (size_t)(row0 + lrow) * DM + kh * 16;
    const __half* ga1 = B + (size_t)(col0 + lrow) * DM + kh * 16;
    const uint32_t ldst = lrow * 80 + kh * 32;

    auto issue = [&](int c) {
        const uint32_t buf = sb + (c & 3) * GST;
        const int k0 = c * 32;
        cp16(buf + ldst,             ga0 + k0);
        cp16(buf + ldst + 16,        ga0 + k0 + 8);
        cp16(buf + GARR + ldst,      ga1 + k0);
        cp16(buf + GARR + ldst + 16, ga1 + k0 + 8);
    };

    issue(0); CP_COMMIT();
    issue(1); CP_COMMIT();
    issue(2); CP_COMMIT();

    const uint32_t aoff = (uint32_t)((wm * 32 + (lane & 15)) * 80
                        + (lane >> 4) * 16);
    const uint32_t boff = (uint32_t)(GARR
                        + (wn * 64 + (lane & 7) + ((lane >> 4) << 3)) * 80
                        + ((lane >> 3) & 1) * 16);

    for (int c = 0; c < 32; c++) {
        CP_WAIT2();
        __syncthreads();
        if (c + 3 < 32) issue(c + 3);
        CP_COMMIT();
        const uint32_t buf = sb + (c & 3) * GST;
        const uint32_t ab = buf + aoff;
        const uint32_t bb = buf + boff;
        #pragma unroll
        for (int ks = 0; ks < 2; ks++) {
            uint32_t ah[2][4];
            ldsm4(ah[0], ab + ks * 32);
            ldsm4(ah[1], ab + 16 * 80 + ks * 32);
            #pragma unroll
            for (int nf2 = 0; nf2 < 4; nf2++) {
                uint32_t bh4[4];
                ldsm4(bh4, bb + nf2 * 16 * 80 + ks * 32);
                #pragma unroll
                for (int mt = 0; mt < 2; mt++) {
                    mma_f16(acc[mt][2 * nf2],     ah[mt], bh4);
                    mma_f16(acc[mt][2 * nf2 + 1], ah[mt], bh4 + 2);
                }
            }
        }
    }

    // ---------------- epilogue ----------------
    const int l4 = lane >> 2, l2 = (lane & 3) * 2;
    if (DO_QKV) {
        const int part = col0 >> 10;                 // 0=q, 1=k, 2=v
        const int head = ((col0 & 1023) >> 6) + wn;
        __half* dhi = (part == 0) ? g_qh : (part == 1) ? g_kh : g_vh;
        #pragma unroll
        for (int mt = 0; mt < 2; mt++) {
            #pragma unroll
            for (int rr = 0; rr < 2; rr++) {
                const int grow = row0 + wm * 32 + mt * 16 + l4 + rr * 8;
                const int b = grow >> 11, s = grow & 2047;
                const size_t obase = ((size_t)(b * NHEAD + head) * SLEN + s) * HD;
                const float* rcp = rc + s * 32;
                const float* rsp = rs + s * 32;
                #pragma unroll
                for (int nf = 0; nf < 8; nf++) {
                    const int d = nf * 8 + l2;
                    const float v1 = acc[mt][nf][rr * 2 + 0];
                    const float v2 = acc[mt][nf][rr * 2 + 1];
                    float ox, oy;
                    if (part < 2) {
                        const int pi = d >> 1;
                        const float cth = rcp[pi], sth = rsp[pi];
                        ox = v1 * cth - v2 * sth;
                        oy = v1 * sth + v2 * cth;
                        if (part == 0) { ox *= SCQ; oy *= SCQ; }
                    } else {
                        ox = v1; oy = v2;
                    }
                    *(uint32_t*)(dhi + obase + d) = packh(ox, oy);
                }
            }
        }
    } else {
        #pragma unroll
        for (int mt = 0; mt < 2; mt++) {
            #pragma unroll
            for (int rr = 0; rr < 2; rr++) {
                const int grow = row0 + wm * 32 + mt * 16 + l4 + rr * 8;
                float* op = outp + (size_t)grow * DM + col0 + wn * 64 + l2;
                #pragma unroll
                for (int nf = 0; nf < 8; nf++) {
                    float2 o;
                    o.x = acc[mt][nf][rr * 2 + 0];
                    o.y = acc[mt][nf][rr * 2 + 1];
                    *(float2*)(op + nf * 8) = o;
                }
            }
        }
    }
}

// ---------------------------------------------------------------------------
// HMMA fp16 FlashAttention: BM=128 queries, KN=128 keys/tile, 256 thr.
// QK: q @ k (1 MMA). PV: p @ v (1 MMA). FFMA exp2 softmax; P stays in
// registers. Diagonal-tile skips (exact).
// smem: 3 tiles (Q, Kh, Vh) of 128 x 72 fp16 (144B stride).
// ---------------------------------------------------------------------------
#define FTILE 18432          // 128*72*2 bytes
__global__ __launch_bounds__(256) void flash_hmma_kernel()
{
    extern __shared__ char fsm[];
    const uint32_t sb = smem_u32(fsm);
    const uint32_t Qt = sb;
    const uint32_t Kh = sb + 1 * FTILE;
    const uint32_t Vh = sb + 2 * FTILE;

    const int tid = threadIdx.x, lane = tid & 31, w = tid >> 5;
    const int qb = gridDim.x - 1 - blockIdx.x;      // long CTAs first
    const int q0 = qb * 128, bh = blockIdx.y;
    const size_t base = (size_t)bh * SLEN * HD;

    const __half *qg  = g_qh + base + (size_t)q0 * HD;
    const __half *khg = g_kh + base;
    const __half *vhg = g_vh + base;

    auto ldone = [&](uint32_t d, const __half* g) {
        #pragma unroll
        for (int kk = 0; kk < 4; kk++) {
            const int c = tid + kk * 256;
            const int row = c >> 3, q8 = c & 7;
            cp16(d + row * 144 + q8 * 16, g + row * 64 + q8 * 8);
        }
    };

    ldone(Qt, qg);
    ldone(Kh, khg);
    CP_COMMIT();
    ldone(Vh, vhg);
    CP_COMMIT();

    uint32_t qf[4][4];
    float oacc[8][4];
    #pragma unroll
    for (int j = 0; j < 8; j++)
        #pragma unroll
        for (int q = 0; q < 4; q++) oacc[j][q] = 0.f;
    float m0 = -1e30f, m1 = -1e30f, l0 = 0.f, l1 = 0.f;

    const int nkb = qb + 1;
    for (int kb = 0; kb < nkb; kb++) {
        const bool lastt = (kb == nkb - 1);
        CP_WAIT1();
        __syncthreads();
        if (kb == 0) {
            #pragma unroll
            for (int ks = 0; ks < 4; ks++) {
                const uint32_t a = (uint32_t)((w * 16 + (lane & 15)) * 144
                                 + (ks * 16 + (lane >> 4) * 8) * 2);
                ldsm4(qf[ks], Qt + a);
            }
        }
        // ---- S = Q @ K^T ----
        float sacc[16][4];
        #pragma unroll
        for (int j = 0; j < 16; j++)
            #pragma unroll
            for (int q = 0; q < 4; q++) sacc[j][q] = 0.f;
        #pragma unroll
        for (int ks = 0; ks < 4; ks++) {
            #pragma unroll
            for (int p = 0; p < 8; p++) {
                if (lastt && p > w) continue;        // fully-masked col group
                uint32_t kh4[4];
                const uint32_t a = (uint32_t)((p * 16 + (lane & 15)) * 144
                                 + (ks * 16 + (lane >> 4) * 8) * 2);
                ldsm4(kh4, Kh + a);
                uint32_t bh0[2] = {kh4[0], kh4[2]}, bh1[2] = {kh4[1], kh4[3]};
                mma_f16(sacc[2 * p],     qf[ks], bh0);
                mma_f16(sacc[2 * p + 1], qf[ks], bh1);
            }
        }
        __syncthreads();                 // all warps done reading K smem
        if (!lastt) {
            ldone(Kh, khg + (size_t)(kb + 1) * 128 * HD);
            CP_COMMIT();
        }

        // ---- softmax (registers only; overlaps with K prefetch) ----
        if (lastt) {  // diagonal tile: mask col > row (tile-local, kb*128==q0)
            const int rl0 = w * 16 + (lane >> 2);
            #pragma unroll
            for (int j = 0; j < 16; j++) {
                const int c = j * 8 + (lane & 3) * 2;
                if (c     > rl0)     sacc[j][0] = -1e30f;
                if (c + 1 > rl0)     sacc[j][1] = -1e30f;
                if (c     > rl0 + 8) sacc[j][2] = -1e30f;
                if (c + 1 > rl0 + 8) sacc[j][3] = -1e30f;
            }
        }
        float rmx0 = -1e30f, rmx1 = -1e30f;
        #pragma unroll
        for (int j = 0; j < 16; j++) {
            rmx0 = fmaxf(rmx0, fmaxf(sacc[j][0], sacc[j][1]));
            rmx1 = fmaxf(rmx1, fmaxf(sacc[j][2], sacc[j][3]));
        }
        rmx0 = fmaxf(rmx0, __shfl_xor_sync(0xffffffffu, rmx0, 1));
        rmx0 = fmaxf(rmx0, __shfl_xor_sync(0xffffffffu, rmx0, 2));
        rmx1 = fmaxf(rmx1, __shfl_xor_sync(0xffffffffu, rmx1, 1));
        rmx1 = fmaxf(rmx1, __shfl_xor_sync(0xffffffffu, rmx1, 2));
        const float mn0 = fmaxf(m0, rmx0), mn1 = fmaxf(m1, rmx1);
        const float rs0 = fast_exp2(m0 - mn0), rs1 = fast_exp2(m1 - mn1);
        m0 = mn0; m1 = mn1;
        float sum0 = 0.f, sum1 = 0.f;
        #pragma unroll
        for (int j = 0; j < 16; j++) {
            sacc[j][0] = fast_exp2(sacc[j][0] - m0);
            sacc[j][1] = fast_exp2(sacc[j][1] - m0);
            sacc[j][2] = fast_exp2(sacc[j][2] - m1);
            sacc[j][3] = fast_exp2(sacc[j][3] - m1);
            sum0 += sacc[j][0] + sacc[j][1];
            sum1 += sacc[j][2] + sacc[j][3];
        }
        sum0 += __shfl_xor_sync(0xffffffffu, sum0, 1);
        sum0 += __shfl_xor_sync(0xffffffffu, sum0, 2);
        sum1 += __shfl_xor_sync(0xffffffffu, sum1, 1);
        sum1 += __shfl_xor_sync(0xffffffffu, sum1, 2);
        l0 = l0 * rs0 + sum0;
        l1 = l1 * rs1 + sum1;
        #pragma unroll
        for (int j = 0; j < 8; j++) {
            oacc[j][0] *= rs0; oacc[j][1] *= rs0;
            oacc[j][2] *= rs1; oacc[j][3] *= rs1;
        }

        // ---- O += P @ V ----
        if (!lastt) CP_WAIT1(); else CP_WAIT0();
        __syncthreads();
        #pragma unroll
        for (int ks = 0; ks < 8; ks++) {
            if (lastt && ks > w) continue;           // P ~ 0 beyond diagonal
            const float* s0 = sacc[2 * ks];
            const float* s1 = sacc[2 * ks + 1];
            uint32_t ph[4];
            ph[0] = packh(s0[0], s0[1]); ph[1] = packh(s0[2], s0[3]);
            ph[2] = packh(s1[0], s1[1]); ph[3] = packh(s1[2], s1[3]);
            #pragma unroll
            for (int p = 0; p < 4; p++) {
                uint32_t vh4[4];
                const uint32_t a = (uint32_t)((ks * 16 + (lane & 15)) * 144
                                 + (p * 16 + (lane >> 4) * 8) * 2);
                ldsm4t(vh4, Vh + a);
                uint32_t bh0[2] = {vh4[0], vh4[1]}, bh1[2] = {vh4[2], vh4[3]};
                mma_f16(oacc[2 * p],     ph, bh0);
                mma_f16(oacc[2 * p + 1], ph, bh1);
            }
        }
        __syncthreads();                 // all warps done reading V smem
        if (!lastt) {
            ldone(Vh, vhg + (size_t)(kb + 1) * 128 * HD);
            CP_COMMIT();
        }
    }

    // ---- epilogue: normalize, write fp16 [B,S,D] ----
    const float inv0 = 1.f / l0, inv1 = 1.f / l1;
    const int b = bh >> 4, h = bh & 15;
    const int s0r = q0 + w * 16 + (lane >> 2);
    const size_t rowA = (size_t)(b * SLEN + s0r);
    const size_t rowB = rowA + 8;
    const int colb = h * 64 + (lane & 3) * 2;
    #pragma unroll
    for (int j = 0; j < 8; j++) {
        const int col = colb + j * 8;
        *(uint32_t*)(g_ah + rowA * DM + col) =
            packh(oacc[j][0] * inv0, oacc[j][1] * inv0);
        *(uint32_t*)(g_ah + rowB * DM + col) =
            packh(oacc[j][2] * inv1, oacc[j][3] * inv1);
    }
}

// ---------------------------------------------------------------------------
extern "C" void kernel_launch(void* const* d_in, const int* in_sizes, int n_in,
                              void* d_out, int out_size)
{
    const float* x    = (const float*)d_in[0];
    const float* rc   = (const float*)d_in[1];
    const float* rs   = (const float*)d_in[2];
    const float* Wqkv = (const float*)d_in[3];
    const float* Wout = (const float*)d_in[4];
    float* out = (float*)d_out;

    const size_t mma_sh   = 4 * GST;     // 81920
    const size_t flash_sh = 3 * FTILE;   // 55296
    cudaFuncSetAttribute(hmma_gemm_kernel<1>,
        cudaFuncAttributeMaxDynamicSharedMemorySize, (int)mma_sh);
    cudaFuncSetAttribute(hmma_gemm_kernel<0>,
        cudaFuncAttributeMaxDynamicSharedMemorySize, (int)mma_sh);
    cudaFuncSetAttribute(flash_hmma_kernel,
        cudaFuncAttributeMaxDynamicSharedMemorySize, (int)flash_sh);

    __half *xh, *ah, *wqh, *woh;
    cudaGetSymbolAddress((void**)&xh,  g_xh);
    cudaGetSymbolAddress((void**)&ah,  g_ah);
    cudaGetSymbolAddress((void**)&wqh, g_wqh);
    cudaGetSymbolAddress((void**)&woh, g_woh);

    // 1. converts / transposes
    conv_x_kernel<<<(NROWS * DM) / 1024, 256>>>(x, xh, NROWS * DM);
    conv_wt_kernel<<<dim3(96, 32), 256>>>(Wqkv, wqh, 3 * DM);
    conv_wt_kernel<<<dim3(32, 32), 256>>>(Wout, woh, DM);

    // 2. QKV GEMM (fp16 HMMA) + fused RoPE + scatter
    hmma_gemm_kernel<1><<<dim3(24, 32), 256, mma_sh>>>(
        xh, wqh, rc, rs, nullptr);

    // 3. flash attention (fp16 HMMA) -> g_ah
    flash_hmma_kernel<<<dim3(SLEN / 128, BATCH * NHEAD), 256, flash_sh>>>();

    // 4. out-projection GEMM (fp16 HMMA)
    hmma_gemm_kernel<0><<<dim3(8, 32), 256, mma_sh>>>(
        ah, woh, nullptr, nullptr, out);
}

// round 15
// speedup vs baseline: 1.5212x; 1.5212x over previous
#include <cuda_runtime.h>
#include <cuda_fp16.h>
#include <math.h>
#include <stdint.h>

#define SLEN 2048
#define DM   1024
#define NHEAD 16
#define HD   64
#define BATCH 2
#define NROWS (BATCH*SLEN)   // 4096

// ---------------- scratch (device globals; no allocation allowed) ----------
__device__ __half g_xh[(size_t)NROWS*DM];          // x fp16
__device__ __half g_ah[(size_t)NROWS*DM];          // attn out fp16
__device__ __half g_wqh[(size_t)3*DM*DM];          // W_qkv^T fp16 [3072,1024]
__device__ __half g_woh[(size_t)DM*DM];            // W_out^T fp16
// q/k/v fp16, layout [B*H][S][64]
__device__ __half g_qh[(size_t)BATCH*NHEAD*SLEN*HD];
__device__ __half g_kh[(size_t)BATCH*NHEAD*SLEN*HD];
__device__ __half g_vh[(size_t)BATCH*NHEAD*SLEN*HD];

// ---------------- baseline-PTX helpers -------------------------------------
__device__ __forceinline__ uint32_t smem_u32(const void* p) {
    uint32_t a;
    asm("{ .reg .u64 t; cvta.to.shared.u64 t, %1; cvt.u32.u64 %0, t; }"
        : "=r"(a) : "l"(p));
    return a;
}
__device__ __forceinline__ void cp16(uint32_t s, const void* g) {
    asm volatile("cp.async.cg.shared.global [%0], [%1], 16;"
                 :: "r"(s), "l"(g) : "memory");
}
#define CP_COMMIT() asm volatile("cp.async.commit_group;" ::: "memory")
#define CP_WAIT2()  asm volatile("cp.async.wait_group 2;" ::: "memory")
#define CP_WAIT1()  asm volatile("cp.async.wait_group 1;" ::: "memory")
#define CP_WAIT0()  asm volatile("cp.async.wait_group 0;" ::: "memory")

__device__ __forceinline__ void ldsm4(uint32_t* r, uint32_t addr) {
    asm volatile("ldmatrix.sync.aligned.m8n8.x4.shared.b16 {%0,%1,%2,%3}, [%4];"
        : "=r"(r[0]), "=r"(r[1]), "=r"(r[2]), "=r"(r[3]) : "r"(addr));
}
__device__ __forceinline__ void ldsm4t(uint32_t* r, uint32_t addr) {
    asm volatile("ldmatrix.sync.aligned.m8n8.x4.trans.shared.b16 {%0,%1,%2,%3}, [%4];"
        : "=r"(r[0]), "=r"(r[1]), "=r"(r[2]), "=r"(r[3]) : "r"(addr));
}
// fp16 MMA, fp32 accumulate
__device__ __forceinline__ void mma_f16(float* d, const uint32_t* a,
                                        const uint32_t* b) {
    asm volatile("mma.sync.aligned.m16n8k16.row.col.f32.f16.f16.f32 "
        "{%0,%1,%2,%3}, {%4,%5,%6,%7}, {%8,%9}, {%0,%1,%2,%3};"
        : "+f"(d[0]), "+f"(d[1]), "+f"(d[2]), "+f"(d[3])
        : "r"(a[0]), "r"(a[1]), "r"(a[2]), "r"(a[3]), "r"(b[0]), "r"(b[1]));
}
// pack two fp32 -> half2 (first arg in low half)
__device__ __forceinline__ uint32_t packh(float lo, float hi) {
    __half2 h = __floats2half2_rn(lo, hi);
    return *reinterpret_cast<uint32_t*>(&h);
}

// exp2 via FFMA poly (no MUFU). z expected <= 0; clamped at -40.
__device__ __forceinline__ float fast_exp2(float z) {
    z = fmaxf(z, -40.f);
    const float km = z + 12582912.f;          // round-to-nearest int
    const int   ki = __float_as_int(km) - 0x4B400000;   // = round(z)
    const float f  = z - (km - 12582912.f);   // frac in [-0.5, 0.5]
    float p = 0.0013333558f;
    p = fmaf(p, f, 0.0096181815f);
    p = fmaf(p, f, 0.0555041087f);
    p = fmaf(p, f, 0.2402265069f);
    p = fmaf(p, f, 0.6931471806f);
    p = fmaf(p, f, 1.0f);
    return p * __int_as_float((ki + 127) << 23);
}

#define SCQ   0.18033688011112042f   // hd^-0.5 * log2(e), folded into Q

// ---------------------------------------------------------------------------
// Convert fp32 -> fp16 (activations; single precision level)
// ---------------------------------------------------------------------------
__global__ __launch_bounds__(256) void conv_x_kernel(
    const float* __restrict__ src, __half* __restrict__ dst, int n)
{
    int i = (blockIdx.x * 256 + threadIdx.x) * 4;
    if (i >= n) return;
    float4 v = *(const float4*)(src + i);
    uint2 o;
    o.x = packh(v.x, v.y);
    o.y = packh(v.z, v.w);
    *(uint2*)(dst + i) = o;
}

// ---------------------------------------------------------------------------
// Transpose: W[1024, N] fp32 -> Wt [N, 1024] fp16
// ---------------------------------------------------------------------------
__global__ __launch_bounds__(256) void conv_wt_kernel(
    const float* __restrict__ W, __half* __restrict__ hi, int N)
{
    __shared__ float t[32][33];
    const int n0 = blockIdx.x * 32, k0 = blockIdx.y * 32;
    const int tx = threadIdx.x & 31, ty = threadIdx.x >> 5;
    #pragma unroll
    for (int i = 0; i < 4; i++)
        t[ty + i * 8][tx] = W[(size_t)(k0 + ty + i * 8) * N + n0 + tx];
    __syncthreads();
    #pragma unroll
    for (int i = 0; i < 4; i++) {
        const int n = n0 + ty + i * 8;
        hi[(size_t)n * DM + k0 + tx] = __float2half_rn(t[tx][ty + i * 8]);
    }
}

// ---------------------------------------------------------------------------
// HMMA pure-fp16 GEMM: D = A * B^T, 128x128 CTA tile, 8 warps (4m x 2n),
// m16n8k16, K-chunk 32, 4-stage single-sync cp.async pipeline.
// Stage = 2 arrays x 128 rows x 80B = 20480B; 4 stages = 80KB -> 2 CTAs/SM.
// DO_QKV: fused RoPE + fp16 scatter to g_q/k/v.
// ---------------------------------------------------------------------------
#define GST   20480
#define GARR  10240
template<int DO_QKV>
__global__ __launch_bounds__(256, 2) void hmma_gemm_kernel(
    const __half* __restrict__ A, const __half* __restrict__ B,
    const float* __restrict__ rc, const float* __restrict__ rs,
    float* __restrict__ outp)
{
    extern __shared__ char smem[];
    const uint32_t sb = smem_u32(smem);
    const int tid = threadIdx.x, lane = tid & 31, wid = tid >> 5;
    const int wm = wid >> 1, wn = wid & 1;
    const int row0 = blockIdx.y * 128, col0 = blockIdx.x * 128;

    float acc[2][8][4];
    #pragma unroll
    for (int m = 0; m < 2; m++)
        #pragma unroll
        for (int n = 0; n < 8; n++)
            #pragma unroll
            for (int q = 0; q < 4; q++) acc[m][n][q] = 0.f;

    const int lrow = tid >> 1, kh = tid & 1;
    const __half* ga0 = A + (size_t)(row0 + lrow) * DM + kh * 16;
    const __half* ga1 = B + (size_t)(col0 + lrow) * DM + kh * 16;
    const uint32_t ldst = lrow * 80 + kh * 32;

    auto issue = [&](int c) {
        const uint32_t buf = sb + (c & 3) * GST;
        const int k0 = c * 32;
        cp16(buf + ldst,             ga0 + k0);
        cp16(buf + ldst + 16,        ga0 + k0 + 8);
        cp16(buf + GARR + ldst,      ga1 + k0);
        cp16(buf + GARR + ldst + 16, ga1 + k0 + 8);
    };

    issue(0); CP_COMMIT();
    issue(1); CP_COMMIT();
    issue(2); CP_COMMIT();

    const uint32_t aoff = (uint32_t)((wm * 32 + (lane & 15)) * 80
                        + (lane >> 4) * 16);
    const uint32_t boff = (uint32_t)(GARR
                        + (wn * 64 + (lane & 7) + ((lane >> 4) << 3)) * 80
                        + ((lane >> 3) & 1) * 16);

    for (int c = 0; c < 32; c++) {
        CP_WAIT2();
        __syncthreads();
        if (c + 3 < 32) issue(c + 3);
        CP_COMMIT();
        const uint32_t buf = sb + (c & 3) * GST;
        const uint32_t ab = buf + aoff;
        const uint32_t bb = buf + boff;
        #pragma unroll
        for (int ks = 0; ks < 2; ks++) {
            uint32_t ah[2][4];
            ldsm4(ah[0], ab + ks * 32);
            ldsm4(ah[1], ab + 16 * 80 + ks * 32);
            #pragma unroll
            for (int nf2 = 0; nf2 < 4; nf2++) {
                uint32_t bh4[4];
                ldsm4(bh4, bb + nf2 * 16 * 80 + ks * 32);
                #pragma unroll
                for (int mt = 0; mt < 2; mt++) {
                    mma_f16(acc[mt][2 * nf2],     ah[mt], bh4);
                    mma_f16(acc[mt][2 * nf2 + 1], ah[mt], bh4 + 2);
                }
            }
        }
    }

    // ---------------- epilogue ----------------
    const int l4 = lane >> 2, l2 = (lane & 3) * 2;
    if (DO_QKV) {
        const int part = col0 >> 10;                 // 0=q, 1=k, 2=v
        const int head = ((col0 & 1023) >> 6) + wn;
        __half* dhi = (part == 0) ? g_qh : (part == 1) ? g_kh : g_vh;
        #pragma unroll
        for (int mt = 0; mt < 2; mt++) {
            #pragma unroll
            for (int rr = 0; rr < 2; rr++) {
                const int grow = row0 + wm * 32 + mt * 16 + l4 + rr * 8;
                const int b = grow >> 11, s = grow & 2047;
                const size_t obase = ((size_t)(b * NHEAD + head) * SLEN + s) * HD;
                const float* rcp = rc + s * 32;
                const float* rsp = rs + s * 32;
                #pragma unroll
                for (int nf = 0; nf < 8; nf++) {
                    const int d = nf * 8 + l2;
                    const float v1 = acc[mt][nf][rr * 2 + 0];
                    const float v2 = acc[mt][nf][rr * 2 + 1];
                    float ox, oy;
                    if (part < 2) {
                        const int pi = d >> 1;
                        const float cth = rcp[pi], sth = rsp[pi];
                        ox = v1 * cth - v2 * sth;
                        oy = v1 * sth + v2 * cth;
                        if (part == 0) { ox *= SCQ; oy *= SCQ; }
                    } else {
                        ox = v1; oy = v2;
                    }
                    *(uint32_t*)(dhi + obase + d) = packh(ox, oy);
                }
            }
        }
    } else {
        #pragma unroll
        for (int mt = 0; mt < 2; mt++) {
            #pragma unroll
            for (int rr = 0; rr < 2; rr++) {
                const int grow = row0 + wm * 32 + mt * 16 + l4 + rr * 8;
                float* op = outp + (size_t)grow * DM + col0 + wn * 64 + l2;
                #pragma unroll
                for (int nf = 0; nf < 8; nf++) {
                    float2 o;
                    o.x = acc[mt][nf][rr * 2 + 0];
                    o.y = acc[mt][nf][rr * 2 + 1];
                    *(float2*)(op + nf * 8) = o;
                }
            }
        }
    }
}

// ---------------------------------------------------------------------------
// HMMA fp16 FlashAttention: BM=128 queries, KN=128 keys/tile, 256 thr.
// QK: q @ k (1 MMA). PV: p @ v (1 MMA). FFMA exp2 softmax; P stays in
// registers. Diagonal-tile skips (exact).
// smem: 3 tiles (Q, Kh, Vh) of 128 x 72 fp16 (144B stride).
// ---------------------------------------------------------------------------
#define FTILE 18432          // 128*72*2 bytes
__global__ __launch_bounds__(256) void flash_hmma_kernel()
{
    extern __shared__ char fsm[];
    const uint32_t sb = smem_u32(fsm);
    const uint32_t Qt = sb;
    const uint32_t Kh = sb + 1 * FTILE;
    const uint32_t Vh = sb + 2 * FTILE;

    const int tid = threadIdx.x, lane = tid & 31, w = tid >> 5;
    const int qb = gridDim.x - 1 - blockIdx.x;      // long CTAs first
    const int q0 = qb * 128, bh = blockIdx.y;
    const size_t base = (size_t)bh * SLEN * HD;

    const __half *qg  = g_qh + base + (size_t)q0 * HD;
    const __half *khg = g_kh + base;
    const __half *vhg = g_vh + base;

    auto ldone = [&](uint32_t d, const __half* g) {
        #pragma unroll
        for (int kk = 0; kk < 4; kk++) {
            const int c = tid + kk * 256;
            const int row = c >> 3, q8 = c & 7;
            cp16(d + row * 144 + q8 * 16, g + row * 64 + q8 * 8);
        }
    };

    ldone(Qt, qg);
    ldone(Kh, khg);
    CP_COMMIT();
    ldone(Vh, vhg);
    CP_COMMIT();

    uint32_t qf[4][4];
    float oacc[8][4];
    #pragma unroll
    for (int j = 0; j < 8; j++)
        #pragma unroll
        for (int q = 0; q < 4; q++) oacc[j][q] = 0.f;
    float m0 = -1e30f, m1 = -1e30f, l0 = 0.f, l1 = 0.f;

    const int nkb = qb + 1;
    for (int kb = 0; kb < nkb; kb++) {
        const bool lastt = (kb == nkb - 1);
        CP_WAIT1();
        __syncthreads();
        if (kb == 0) {
            #pragma unroll
            for (int ks = 0; ks < 4; ks++) {
                const uint32_t a = (uint32_t)((w * 16 + (lane & 15)) * 144
                                 + (ks * 16 + (lane >> 4) * 8) * 2);
                ldsm4(qf[ks], Qt + a);
            }
        }
        // ---- S = Q @ K^T ----
        float sacc[16][4];
        #pragma unroll
        for (int j = 0; j < 16; j++)
            #pragma unroll
            for (int q = 0; q < 4; q++) sacc[j][q] = 0.f;
        #pragma unroll
        for (int ks = 0; ks < 4; ks++) {
            #pragma unroll
            for (int p = 0; p < 8; p++) {
                if (lastt && p > w) continue;        // fully-masked col group
                uint32_t kh4[4];
                const uint32_t a = (uint32_t)((p * 16 + (lane & 15)) * 144
                                 + (ks * 16 + (lane >> 4) * 8) * 2);
                ldsm4(kh4, Kh + a);
                uint32_t bh0[2] = {kh4[0], kh4[2]}, bh1[2] = {kh4[1], kh4[3]};
                mma_f16(sacc[2 * p],     qf[ks], bh0);
                mma_f16(sacc[2 * p + 1], qf[ks], bh1);
            }
        }
        __syncthreads();                 // all warps done reading K smem
        if (!lastt) {
            ldone(Kh, khg + (size_t)(kb + 1) * 128 * HD);
            CP_COMMIT();
        }

        // ---- softmax (registers only; overlaps with K prefetch) ----
        if (lastt) {  // diagonal tile: mask col > row (tile-local, kb*128==q0)
            const int rl0 = w * 16 + (lane >> 2);
            #pragma unroll
            for (int j = 0; j < 16; j++) {
                const int c = j * 8 + (lane & 3) * 2;
                if (c     > rl0)     sacc[j][0] = -1e30f;
                if (c + 1 > rl0)     sacc[j][1] = -1e30f;
                if (c     > rl0 + 8) sacc[j][2] = -1e30f;
                if (c + 1 > rl0 + 8) sacc[j][3] = -1e30f;
            }
        }
        float rmx0 = -1e30f, rmx1 = -1e30f;
        #pragma unroll
        for (int j = 0; j < 16; j++) {
            rmx0 = fmaxf(rmx0, fmaxf(sacc[j][0], sacc[j][1]));
            rmx1 = fmaxf(rmx1, fmaxf(sacc[j][2], sacc[j][3]));
        }
        rmx0 = fmaxf(rmx0, __shfl_xor_sync(0xffffffffu, rmx0, 1));
        rmx0 = fmaxf(rmx0, __shfl_xor_sync(0xffffffffu, rmx0, 2));
        rmx1 = fmaxf(rmx1, __shfl_xor_sync(0xffffffffu, rmx1, 1));
        rmx1 = fmaxf(rmx1, __shfl_xor_sync(0xffffffffu, rmx1, 2));
        const float mn0 = fmaxf(m0, rmx0), mn1 = fmaxf(m1, rmx1);
        const float rs0 = fast_exp2(m0 - mn0), rs1 = fast_exp2(m1 - mn1);
        m0 = mn0; m1 = mn1;
        float sum0 = 0.f, sum1 = 0.f;
        #pragma unroll
        for (int j = 0; j < 16; j++) {
            sacc[j][0] = fast_exp2(sacc[j][0] - m0);
            sacc[j][1] = fast_exp2(sacc[j][1] - m0);
            sacc[j][2] = fast_exp2(sacc[j][2] - m1);
            sacc[j][3] = fast_exp2(sacc[j][3] - m1);
            sum0 += sacc[j][0] + sacc[j][1];
            sum1 += sacc[j][2] + sacc[j][3];
        }
        sum0 += __shfl_xor_sync(0xffffffffu, sum0, 1);
        sum0 += __shfl_xor_sync(0xffffffffu, sum0, 2);
        sum1 += __shfl_xor_sync(0xffffffffu, sum1, 1);
        sum1 += __shfl_xor_sync(0xffffffffu, sum1, 2);
        l0 = l0 * rs0 + sum0;
        l1 = l1 * rs1 + sum1;
        #pragma unroll
        for (int j = 0; j < 8; j++) {
            oacc[j][0] *= rs0; oacc[j][1] *= rs0;
            oacc[j][2] *= rs1; oacc[j][3] *= rs1;
        }

        // ---- O += P @ V ----
        if (!lastt) CP_WAIT1(); else CP_WAIT0();
        __syncthreads();
        #pragma unroll
        for (int ks = 0; ks < 8; ks++) {
            if (lastt && ks > w) continue;           // P ~ 0 beyond diagonal
            const float* s0 = sacc[2 * ks];
            const float* s1 = sacc[2 * ks + 1];
            uint32_t ph[4];
            ph[0] = packh(s0[0], s0[1]); ph[1] = packh(s0[2], s0[3]);
            ph[2] = packh(s1[0], s1[1]); ph[3] = packh(s1[2], s1[3]);
            #pragma unroll
            for (int p = 0; p < 4; p++) {
                uint32_t vh4[4];
                const uint32_t a = (uint32_t)((ks * 16 + (lane & 15)) * 144
                                 + (p * 16 + (lane >> 4) * 8) * 2);
                ldsm4t(vh4, Vh + a);
                uint32_t bh0[2] = {vh4[0], vh4[1]}, bh1[2] = {vh4[2], vh4[3]};
                mma_f16(oacc[2 * p],     ph, bh0);
                mma_f16(oacc[2 * p + 1], ph, bh1);
            }
        }
        __syncthreads();                 // all warps done reading V smem
        if (!lastt) {
            ldone(Vh, vhg + (size_t)(kb + 1) * 128 * HD);
            CP_COMMIT();
        }
    }

    // ---- epilogue: normalize, write fp16 [B,S,D] ----
    const float inv0 = 1.f / l0, inv1 = 1.f / l1;
    const int b = bh >> 4, h = bh & 15;
    const int s0r = q0 + w * 16 + (lane >> 2);
    const size_t rowA = (size_t)(b * SLEN + s0r);
    const size_t rowB = rowA + 8;
    const int colb = h * 64 + (lane & 3) * 2;
    #pragma unroll
    for (int j = 0; j < 8; j++) {
        const int col = colb + j * 8;
        *(uint32_t*)(g_ah + rowA * DM + col) =
            packh(oacc[j][0] * inv0, oacc[j][1] * inv0);
        *(uint32_t*)(g_ah + rowB * DM + col) =
            packh(oacc[j][2] * inv1, oacc[j][3] * inv1);
    }
}

// ---------------------------------------------------------------------------
extern "C" void kernel_launch(void* const* d_in, const int* in_sizes, int n_in,
                              void* d_out, int out_size)
{
    const float* x    = (const float*)d_in[0];
    const float* rc   = (const float*)d_in[1];
    const float* rs   = (const float*)d_in[2];
    const float* Wqkv = (const float*)d_in[3];
    const float* Wout = (const float*)d_in[4];
    float* out = (float*)d_out;

    const size_t mma_sh   = 4 * GST;     // 81920
    const size_t flash_sh = 3 * FTILE;   // 55296
    cudaFuncSetAttribute(hmma_gemm_kernel<1>,
        cudaFuncAttributeMaxDynamicSharedMemorySize, (int)mma_sh);
    cudaFuncSetAttribute(hmma_gemm_kernel<0>,
        cudaFuncAttributeMaxDynamicSharedMemorySize, (int)mma_sh);
    cudaFuncSetAttribute(flash_hmma_kernel,
        cudaFuncAttributeMaxDynamicSharedMemorySize, (int)flash_sh);

    __half *xh, *ah, *wqh, *woh;
    cudaGetSymbolAddress((void**)&xh,  g_xh);
    cudaGetSymbolAddress((void**)&ah,  g_ah);
    cudaGetSymbolAddress((void**)&wqh, g_wqh);
    cudaGetSymbolAddress((void**)&woh, g_woh);

    // 1. converts / transposes
    conv_x_kernel<<<(NROWS * DM) / 1024, 256>>>(x, xh, NROWS * DM);
    conv_wt_kernel<<<dim3(96, 32), 256>>>(Wqkv, wqh, 3 * DM);
    conv_wt_kernel<<<dim3(32, 32), 256>>>(Wout, woh, DM);

    // 2. QKV GEMM (fp16 HMMA) + fused RoPE + scatter
    hmma_gemm_kernel<1><<<dim3(24, 32), 256, mma_sh>>>(
        xh, wqh, rc, rs, nullptr);

    // 3. flash attention (fp16 HMMA) -> g_ah
    flash_hmma_kernel<<<dim3(SLEN / 128, BATCH * NHEAD), 256, flash_sh>>>();

    // 4. out-projection GEMM (fp16 HMMA)
    hmma_gemm_kernel<0><<<dim3(8, 32), 256, mma_sh>>>(
        ah, woh, nullptr, nullptr, out);
}

// round 16
// speedup vs baseline: 1.5434x; 1.0146x over previous
#include <cuda_runtime.h>
#include <cuda_fp16.h>
#include <math.h>
#include <stdint.h>

#define SLEN 2048
#define DM   1024
#define NHEAD 16
#define HD   64
#define BATCH 2
#define NROWS (BATCH*SLEN)   // 4096

// ---------------- scratch (device globals; no allocation allowed) ----------
__device__ __half g_xh[(size_t)NROWS*DM];          // x fp16
__device__ __half g_ah[(size_t)NROWS*DM];          // attn out fp16
__device__ __half g_wqh[(size_t)3*DM*DM];          // W_qkv^T fp16 [3072,1024]
__device__ __half g_woh[(size_t)DM*DM];            // W_out^T fp16
// q/k/v fp16, layout [B*H][S][64]
__device__ __half g_qh[(size_t)BATCH*NHEAD*SLEN*HD];
__device__ __half g_kh[(size_t)BATCH*NHEAD*SLEN*HD];
__device__ __half g_vh[(size_t)BATCH*NHEAD*SLEN*HD];

// ---------------- baseline-PTX helpers -------------------------------------
__device__ __forceinline__ uint32_t smem_u32(const void* p) {
    uint32_t a;
    asm("{ .reg .u64 t; cvta.to.shared.u64 t, %1; cvt.u32.u64 %0, t; }"
        : "=r"(a) : "l"(p));
    return a;
}
__device__ __forceinline__ void cp16(uint32_t s, const void* g) {
    asm volatile("cp.async.cg.shared.global [%0], [%1], 16;"
                 :: "r"(s), "l"(g) : "memory");
}
#define CP_COMMIT() asm volatile("cp.async.commit_group;" ::: "memory")
#define CP_WAIT2()  asm volatile("cp.async.wait_group 2;" ::: "memory")
#define CP_WAIT1()  asm volatile("cp.async.wait_group 1;" ::: "memory")
#define CP_WAIT0()  asm volatile("cp.async.wait_group 0;" ::: "memory")

__device__ __forceinline__ void ldsm4(uint32_t* r, uint32_t addr) {
    asm volatile("ldmatrix.sync.aligned.m8n8.x4.shared.b16 {%0,%1,%2,%3}, [%4];"
        : "=r"(r[0]), "=r"(r[1]), "=r"(r[2]), "=r"(r[3]) : "r"(addr));
}
__device__ __forceinline__ void ldsm4t(uint32_t* r, uint32_t addr) {
    asm volatile("ldmatrix.sync.aligned.m8n8.x4.trans.shared.b16 {%0,%1,%2,%3}, [%4];"
        : "=r"(r[0]), "=r"(r[1]), "=r"(r[2]), "=r"(r[3]) : "r"(addr));
}
// fp16 MMA, fp32 accumulate
__device__ __forceinline__ void mma_f16(float* d, const uint32_t* a,
                                        const uint32_t* b) {
    asm volatile("mma.sync.aligned.m16n8k16.row.col.f32.f16.f16.f32 "
        "{%0,%1,%2,%3}, {%4,%5,%6,%7}, {%8,%9}, {%0,%1,%2,%3};"
        : "+f"(d[0]), "+f"(d[1]), "+f"(d[2]), "+f"(d[3])
        : "r"(a[0]), "r"(a[1]), "r"(a[2]), "r"(a[3]), "r"(b[0]), "r"(b[1]));
}
// pack two fp32 -> half2 (first arg in low half)
__device__ __forceinline__ uint32_t packh(float lo, float hi) {
    __half2 h = __floats2half2_rn(lo, hi);
    return *reinterpret_cast<uint32_t*>(&h);
}

// exp2 via FFMA poly (no MUFU). z expected <= 0; clamped at -40.
__device__ __forceinline__ float fast_exp2(float z) {
    z = fmaxf(z, -40.f);
    const float km = z + 12582912.f;          // round-to-nearest int
    const int   ki = __float_as_int(km) - 0x4B400000;   // = round(z)
    const float f  = z - (km - 12582912.f);   // frac in [-0.5, 0.5]
    float p = 0.0013333558f;
    p = fmaf(p, f, 0.0096181815f);
    p = fmaf(p, f, 0.0555041087f);
    p = fmaf(p, f, 0.2402265069f);
    p = fmaf(p, f, 0.6931471806f);
    p = fmaf(p, f, 1.0f);
    return p * __int_as_float((ki + 127) << 23);
}

#define SCQ   0.18033688011112042f   // hd^-0.5 * log2(e), folded into Q

// ---------------------------------------------------------------------------
// Convert fp32 -> fp16 (activations; single precision level)
// ---------------------------------------------------------------------------
__global__ __launch_bounds__(256) void conv_x_kernel(
    const float* __restrict__ src, __half* __restrict__ dst, int n)
{
    int i = (blockIdx.x * 256 + threadIdx.x) * 4;
    if (i >= n) return;
    float4 v = *(const float4*)(src + i);
    uint2 o;
    o.x = packh(v.x, v.y);
    o.y = packh(v.z, v.w);
    *(uint2*)(dst + i) = o;
}

// ---------------------------------------------------------------------------
// Transpose: W[1024, N] fp32 -> Wt [N, 1024] fp16
// ---------------------------------------------------------------------------
__global__ __launch_bounds__(256) void conv_wt_kernel(
    const float* __restrict__ W, __half* __restrict__ hi, int N)
{
    __shared__ float t[32][33];
    const int n0 = blockIdx.x * 32, k0 = blockIdx.y * 32;
    const int tx = threadIdx.x & 31, ty = threadIdx.x >> 5;
    #pragma unroll
    for (int i = 0; i < 4; i++)
        t[ty + i * 8][tx] = W[(size_t)(k0 + ty + i * 8) * N + n0 + tx];
    __syncthreads();
    #pragma unroll
    for (int i = 0; i < 4; i++) {
        const int n = n0 + ty + i * 8;
        hi[(size_t)n * DM + k0 + tx] = __float2half_rn(t[tx][ty + i * 8]);
    }
}

// ---------------------------------------------------------------------------
// HMMA pure-fp16 GEMM: D = A * B^T, 128x128 CTA tile, 8 warps (4m x 2n),
// m16n8k16, K-chunk 32, 4-stage single-sync cp.async pipeline.
// Stage = 2 arrays x 128 rows x 80B = 20480B; 4 stages = 80KB -> 2 CTAs/SM.
// DO_QKV: fused RoPE + fp16 scatter to g_q/k/v.
// ---------------------------------------------------------------------------
#define GST   20480
#define GARR  10240
template<int DO_QKV>
__global__ __launch_bounds__(256, 2) void hmma_gemm_kernel(
    const __half* __restrict__ A, const __half* __restrict__ B,
    const float* __restrict__ rc, const float* __restrict__ rs,
    float* __restrict__ outp)
{
    extern __shared__ char smem[];
    const uint32_t sb = smem_u32(smem);
    const int tid = threadIdx.x, lane = tid & 31, wid = tid >> 5;
    const int wm = wid >> 1, wn = wid & 1;
    const int row0 = blockIdx.y * 128, col0 = blockIdx.x * 128;

    float acc[2][8][4];
    #pragma unroll
    for (int m = 0; m < 2; m++)
        #pragma unroll
        for (int n = 0; n < 8; n++)
            #pragma unroll
            for (int q = 0; q < 4; q++) acc[m][n][q] = 0.f;

    const int lrow = tid >> 1, kh = tid & 1;
    const __half* ga0 = A + (size_t)(row0 + lrow) * DM + kh * 16;
    const __half* ga1 = B + (size_t)(col0 + lrow) * DM + kh * 16;
    const uint32_t ldst = lrow * 80 + kh * 32;

    auto issue = [&](int c) {
        const uint32_t buf = sb + (c & 3) * GST;
        const int k0 = c * 32;
        cp16(buf + ldst,             ga0 + k0);
        cp16(buf + ldst + 16,        ga0 + k0 + 8);
        cp16(buf + GARR + ldst,      ga1 + k0);
        cp16(buf + GARR + ldst + 16, ga1 + k0 + 8);
    };

    issue(0); CP_COMMIT();
    issue(1); CP_COMMIT();
    issue(2); CP_COMMIT();

    const uint32_t aoff = (uint32_t)((wm * 32 + (lane & 15)) * 80
                        + (lane >> 4) * 16);
    const uint32_t boff = (uint32_t)(GARR
                        + (wn * 64 + (lane & 7) + ((lane >> 4) << 3)) * 80
                        + ((lane >> 3) & 1) * 16);

    for (int c = 0; c < 32; c++) {
        CP_WAIT2();
        __syncthreads();
        if (c + 3 < 32) issue(c + 3);
        CP_COMMIT();
        const uint32_t buf = sb + (c & 3) * GST;
        const uint32_t ab = buf + aoff;
        const uint32_t bb = buf + boff;
        #pragma unroll
        for (int ks = 0; ks < 2; ks++) {
            uint32_t ah[2][4];
            ldsm4(ah[0], ab + ks * 32);
            ldsm4(ah[1], ab + 16 * 80 + ks * 32);
            #pragma unroll
            for (int nf2 = 0; nf2 < 4; nf2++) {
                uint32_t bh4[4];
                ldsm4(bh4, bb + nf2 * 16 * 80 + ks * 32);
                #pragma unroll
                for (int mt = 0; mt < 2; mt++) {
                    mma_f16(acc[mt][2 * nf2],     ah[mt], bh4);
                    mma_f16(acc[mt][2 * nf2 + 1], ah[mt], bh4 + 2);
                }
            }
        }
    }

    // ---------------- epilogue ----------------
    const int l4 = lane >> 2, l2 = (lane & 3) * 2;
    if (DO_QKV) {
        const int part = col0 >> 10;                 // 0=q, 1=k, 2=v
        const int head = ((col0 & 1023) >> 6) + wn;
        __half* dhi = (part == 0) ? g_qh : (part == 1) ? g_kh : g_vh;
        #pragma unroll
        for (int mt = 0; mt < 2; mt++) {
            #pragma unroll
            for (int rr = 0; rr < 2; rr++) {
                const int grow = row0 + wm * 32 + mt * 16 + l4 + rr * 8;
                const int b = grow >> 11, s = grow & 2047;
                const size_t obase = ((size_t)(b * NHEAD + head) * SLEN + s) * HD;
                const float* rcp = rc + s * 32;
                const float* rsp = rs + s * 32;
                #pragma unroll
                for (int nf = 0; nf < 8; nf++) {
                    const int d = nf * 8 + l2;
                    const float v1 = acc[mt][nf][rr * 2 + 0];
                    const float v2 = acc[mt][nf][rr * 2 + 1];
                    float ox, oy;
                    if (part < 2) {
                        const int pi = d >> 1;
                        const float cth = rcp[pi], sth = rsp[pi];
                        ox = v1 * cth - v2 * sth;
                        oy = v1 * sth + v2 * cth;
                        if (part == 0) { ox *= SCQ; oy *= SCQ; }
                    } else {
                        ox = v1; oy = v2;
                    }
                    *(uint32_t*)(dhi + obase + d) = packh(ox, oy);
                }
            }
        }
    } else {
        #pragma unroll
        for (int mt = 0; mt < 2; mt++) {
            #pragma unroll
            for (int rr = 0; rr < 2; rr++) {
                const int grow = row0 + wm * 32 + mt * 16 + l4 + rr * 8;
                float* op = outp + (size_t)grow * DM + col0 + wn * 64 + l2;
                #pragma unroll
                for (int nf = 0; nf < 8; nf++) {
                    float2 o;
                    o.x = acc[mt][nf][rr * 2 + 0];
                    o.y = acc[mt][nf][rr * 2 + 1];
                    *(float2*)(op + nf * 8) = o;
                }
            }
        }
    }
}

// ---------------------------------------------------------------------------
// HMMA fp16 FlashAttention: BM=128 queries, KN=128 keys/tile, 256 thr.
// K and V DOUBLE-BUFFERED: 2 __syncthreads per iteration (no reload guards);
// K_{kb+1} and V_{kb+1} prefetches issue right after the first sync, before
// QK compute. QK: 1 MMA; PV: 1 MMA. FFMA exp2 softmax; P in registers.
// Diagonal-tile skips (exact).
// smem: 5 tiles (Q, K0, K1, V0, V1) of 128 x 72 fp16 (144B stride) = 92160B.
// ---------------------------------------------------------------------------
#define FTILE 18432          // 128*72*2 bytes
__global__ __launch_bounds__(256) void flash_hmma_kernel()
{
    extern __shared__ char fsm[];
    const uint32_t sb = smem_u32(fsm);
    const uint32_t Qt = sb;
    // K buffers at sb + (1 + cb)*FTILE, V buffers at sb + (3 + cb)*FTILE

    const int tid = threadIdx.x, lane = tid & 31, w = tid >> 5;
    const int qb = gridDim.x - 1 - blockIdx.x;      // long CTAs first
    const int q0 = qb * 128, bh = blockIdx.y;
    const size_t base = (size_t)bh * SLEN * HD;

    const __half *qg  = g_qh + base + (size_t)q0 * HD;
    const __half *khg = g_kh + base;
    const __half *vhg = g_vh + base;

    auto ldone = [&](uint32_t d, const __half* g) {
        #pragma unroll
        for (int kk = 0; kk < 4; kk++) {
            const int c = tid + kk * 256;
            const int row = c >> 3, q8 = c & 7;
            cp16(d + row * 144 + q8 * 16, g + row * 64 + q8 * 8);
        }
    };

    ldone(Qt, qg);
    ldone(sb + 1 * FTILE, khg);          // K0
    CP_COMMIT();
    ldone(sb + 3 * FTILE, vhg);          // V0
    CP_COMMIT();

    uint32_t qf[4][4];
    float oacc[8][4];
    #pragma unroll
    for (int j = 0; j < 8; j++)
        #pragma unroll
        for (int q = 0; q < 4; q++) oacc[j][q] = 0.f;
    float m0 = -1e30f, m1 = -1e30f, l0 = 0.f, l1 = 0.f;

    const int nkb = qb + 1;
    for (int kb = 0; kb < nkb; kb++) {
        const bool lastt = (kb == nkb - 1);
        const int cb = kb & 1, nb = cb ^ 1;
        const uint32_t Kcur = sb + (1 + cb) * FTILE;
        const uint32_t Vcur = sb + (3 + cb) * FTILE;

        CP_WAIT1();                      // K_kb arrived (V_kb still pending)
        __syncthreads();                 // sync1: K_kb visible; prev bufs free
        if (!lastt) {                    // prefetch BOTH next tiles now
            ldone(sb + (1 + nb) * FTILE, khg + (size_t)(kb + 1) * 128 * HD);
            CP_COMMIT();
            ldone(sb + (3 + nb) * FTILE, vhg + (size_t)(kb + 1) * 128 * HD);
            CP_COMMIT();
        }
        if (kb == 0) {
            #pragma unroll
            for (int ks = 0; ks < 4; ks++) {
                const uint32_t a = (uint32_t)((w * 16 + (lane & 15)) * 144
                                 + (ks * 16 + (lane >> 4) * 8) * 2);
                ldsm4(qf[ks], Qt + a);
            }
        }
        // ---- S = Q @ K^T ----
        float sacc[16][4];
        #pragma unroll
        for (int j = 0; j < 16; j++)
            #pragma unroll
            for (int q = 0; q < 4; q++) sacc[j][q] = 0.f;
        #pragma unroll
        for (int ks = 0; ks < 4; ks++) {
            #pragma unroll
            for (int p = 0; p < 8; p++) {
                if (lastt && p > w) continue;        // fully-masked col group
                uint32_t kh4[4];
                const uint32_t a = (uint32_t)((p * 16 + (lane & 15)) * 144
                                 + (ks * 16 + (lane >> 4) * 8) * 2);
                ldsm4(kh4, Kcur + a);
                uint32_t bh0[2] = {kh4[0], kh4[2]}, bh1[2] = {kh4[1], kh4[3]};
                mma_f16(sacc[2 * p],     qf[ks], bh0);
                mma_f16(sacc[2 * p + 1], qf[ks], bh1);
            }
        }

        // ---- softmax (registers only; overlaps with prefetches) ----
        if (lastt) {  // diagonal tile: mask col > row (tile-local, kb*128==q0)
            const int rl0 = w * 16 + (lane >> 2);
            #pragma unroll
            for (int j = 0; j < 16; j++) {
                const int c = j * 8 + (lane & 3) * 2;
                if (c     > rl0)     sacc[j][0] = -1e30f;
                if (c + 1 > rl0)     sacc[j][1] = -1e30f;
                if (c     > rl0 + 8) sacc[j][2] = -1e30f;
                if (c + 1 > rl0 + 8) sacc[j][3] = -1e30f;
            }
        }
        float rmx0 = -1e30f, rmx1 = -1e30f;
        #pragma unroll
        for (int j = 0; j < 16; j++) {
            rmx0 = fmaxf(rmx0, fmaxf(sacc[j][0], sacc[j][1]));
            rmx1 = fmaxf(rmx1, fmaxf(sacc[j][2], sacc[j][3]));
        }
        rmx0 = fmaxf(rmx0, __shfl_xor_sync(0xffffffffu, rmx0, 1));
        rmx0 = fmaxf(rmx0, __shfl_xor_sync(0xffffffffu, rmx0, 2));
        rmx1 = fmaxf(rmx1, __shfl_xor_sync(0xffffffffu, rmx1, 1));
        rmx1 = fmaxf(rmx1, __shfl_xor_sync(0xffffffffu, rmx1, 2));
        const float mn0 = fmaxf(m0, rmx0), mn1 = fmaxf(m1, rmx1);
        const float rs0 = fast_exp2(m0 - mn0), rs1 = fast_exp2(m1 - mn1);
        m0 = mn0; m1 = mn1;
        float sum0 = 0.f, sum1 = 0.f;
        #pragma unroll
        for (int j = 0; j < 16; j++) {
            sacc[j][0] = fast_exp2(sacc[j][0] - m0);
            sacc[j][1] = fast_exp2(sacc[j][1] - m0);
            sacc[j][2] = fast_exp2(sacc[j][2] - m1);
            sacc[j][3] = fast_exp2(sacc[j][3] - m1);
            sum0 += sacc[j][0] + sacc[j][1];
            sum1 += sacc[j][2] + sacc[j][3];
        }
        sum0 += __shfl_xor_sync(0xffffffffu, sum0, 1);
        sum0 += __shfl_xor_sync(0xffffffffu, sum0, 2);
        sum1 += __shfl_xor_sync(0xffffffffu, sum1, 1);
        sum1 += __shfl_xor_sync(0xffffffffu, sum1, 2);
        l0 = l0 * rs0 + sum0;
        l1 = l1 * rs1 + sum1;
        #pragma unroll
        for (int j = 0; j < 8; j++) {
            oacc[j][0] *= rs0; oacc[j][1] *= rs0;
            oacc[j][2] *= rs1; oacc[j][3] *= rs1;
        }

        // ---- O += P @ V ----
        if (!lastt) CP_WAIT2(); else CP_WAIT0();   // V_kb arrived
        __syncthreads();                           // sync2: V_kb visible
        #pragma unroll
        for (int ks = 0; ks < 8; ks++) {
            if (lastt && ks > w) continue;           // P ~ 0 beyond diagonal
            const float* s0 = sacc[2 * ks];
            const float* s1 = sacc[2 * ks + 1];
            uint32_t ph[4];
            ph[0] = packh(s0[0], s0[1]); ph[1] = packh(s0[2], s0[3]);
            ph[2] = packh(s1[0], s1[1]); ph[3] = packh(s1[2], s1[3]);
            #pragma unroll
            for (int p = 0; p < 4; p++) {
                uint32_t vh4[4];
                const uint32_t a = (uint32_t)((ks * 16 + (lane & 15)) * 144
                                 + (p * 16 + (lane >> 4) * 8) * 2);
                ldsm4t(vh4, Vcur + a);
                uint32_t bh0[2] = {vh4[0], vh4[1]}, bh1[2] = {vh4[2], vh4[3]};
                mma_f16(oacc[2 * p],     ph, bh0);
                mma_f16(oacc[2 * p + 1], ph, bh1);
            }
        }
    }

    // ---- epilogue: normalize, write fp16 [B,S,D] ----
    const float inv0 = 1.f / l0, inv1 = 1.f / l1;
    const int b = bh >> 4, h = bh & 15;
    const int s0r = q0 + w * 16 + (lane >> 2);
    const size_t rowA = (size_t)(b * SLEN + s0r);
    const size_t rowB = rowA + 8;
    const int colb = h * 64 + (lane & 3) * 2;
    #pragma unroll
    for (int j = 0; j < 8; j++) {
        const int col = colb + j * 8;
        *(uint32_t*)(g_ah + rowA * DM + col) =
            packh(oacc[j][0] * inv0, oacc[j][1] * inv0);
        *(uint32_t*)(g_ah + rowB * DM + col) =
            packh(oacc[j][2] * inv1, oacc[j][3] * inv1);
    }
}

// ---------------------------------------------------------------------------
extern "C" void kernel_launch(void* const* d_in, const int* in_sizes, int n_in,
                              void* d_out, int out_size)
{
    const float* x    = (const float*)d_in[0];
    const float* rc   = (const float*)d_in[1];
    const float* rs   = (const float*)d_in[2];
    const float* Wqkv = (const float*)d_in[3];
    const float* Wout = (const float*)d_in[4];
    float* out = (float*)d_out;

    const size_t mma_sh   = 4 * GST;     // 81920
    const size_t flash_sh = 5 * FTILE;   // 92160
    cudaFuncSetAttribute(hmma_gemm_kernel<1>,
        cudaFuncAttributeMaxDynamicSharedMemorySize, (int)mma_sh);
    cudaFuncSetAttribute(hmma_gemm_kernel<0>,
        cudaFuncAttributeMaxDynamicSharedMemorySize, (int)mma_sh);
    cudaFuncSetAttribute(flash_hmma_kernel,
        cudaFuncAttributeMaxDynamicSharedMemorySize, (int)flash_sh);

    __half *xh, *ah, *wqh, *woh;
    cudaGetSymbolAddress((void**)&xh,  g_xh);
    cudaGetSymbolAddress((void**)&ah,  g_ah);
    cudaGetSymbolAddress((void**)&wqh, g_wqh);
    cudaGetSymbolAddress((void**)&woh, g_woh);

    // 1. converts / transposes
    conv_x_kernel<<<(NROWS * DM) / 1024, 256>>>(x, xh, NROWS * DM);
    conv_wt_kernel<<<dim3(96, 32), 256>>>(Wqkv, wqh, 3 * DM);
    conv_wt_kernel<<<dim3(32, 32), 256>>>(Wout, woh, DM);

    // 2. QKV GEMM (fp16 HMMA) + fused RoPE + scatter
    hmma_gemm_kernel<1><<<dim3(24, 32), 256, mma_sh>>>(
        xh, wqh, rc, rs, nullptr);

    // 3. flash attention (fp16 HMMA) -> g_ah
    flash_hmma_kernel<<<dim3(SLEN / 128, BATCH * NHEAD), 256, flash_sh>>>();

    // 4. out-projection GEMM (fp16 HMMA)
    hmma_gemm_kernel<0><<<dim3(8, 32), 256, mma_sh>>>(
        ah, woh, nullptr, nullptr, out);
}